// round 9
// baseline (speedup 1.0000x reference)
#include <cuda_runtime.h>
#include <cuda_bf16.h>
#include <cstdint>

// ============================ problem constants ============================
#define BATCH 4
#define SEQ   1024
#define HID   4096
#define NHEAD 32
#define HDIM  128
#define M_ROWS (BATCH*SEQ)          // 4096
#define QKV_N  (3*HID)              // 12288
#define KDIM   4096
#define HEAD_ELEMS (BATCH*NHEAD*SEQ*HDIM)  // 16,777,216 per part

// ============================ scratch (device globals) =====================
__device__ float g_qkv[3ull * HEAD_ELEMS];                 // [part][b][h][s][d] fp32
__device__ __nv_bfloat16 g_a1hi[(size_t)M_ROWS * KDIM];    // hidden split  [m][k]
__device__ __nv_bfloat16 g_a1lo[(size_t)M_ROWS * KDIM];
__device__ __nv_bfloat16 g_bphi[(size_t)QKV_N * KDIM];     // W_pack^T split [n][k]
__device__ __nv_bfloat16 g_bplo[(size_t)QKV_N * KDIM];
__device__ __nv_bfloat16 g_bohi[(size_t)HID * KDIM];       // W_o^T split [n][k]
__device__ __nv_bfloat16 g_bolo[(size_t)HID * KDIM];
__device__ __nv_bfloat16 g_athi[(size_t)M_ROWS * HID];     // attn out split [m][k]
__device__ __nv_bfloat16 g_atlo[(size_t)M_ROWS * HID];

// ============================ helpers ======================================
__device__ __forceinline__ uint32_t smem_to_u32(const void* p) {
    uint32_t a;
    asm("{ .reg .u64 t; cvta.to.shared.u64 t, %1; cvt.u32.u64 %0, t; }" : "=r"(a) : "l"(p));
    return a;
}

__device__ __forceinline__ void ldmatrix_x4(uint32_t& r0, uint32_t& r1,
                                            uint32_t& r2, uint32_t& r3, uint32_t addr) {
    asm volatile("ldmatrix.sync.aligned.m8n8.x4.shared.b16 {%0,%1,%2,%3}, [%4];"
                 : "=r"(r0), "=r"(r1), "=r"(r2), "=r"(r3) : "r"(addr));
}

__device__ __forceinline__ void mma_bf16(float* d, const uint32_t* a, uint32_t b0, uint32_t b1) {
    asm volatile(
        "mma.sync.aligned.m16n8k16.row.col.f32.bf16.bf16.f32 "
        "{%0,%1,%2,%3}, {%4,%5,%6,%7}, {%8,%9}, {%0,%1,%2,%3};"
        : "+f"(d[0]), "+f"(d[1]), "+f"(d[2]), "+f"(d[3])
        : "r"(a[0]), "r"(a[1]), "r"(a[2]), "r"(a[3]), "r"(b0), "r"(b1));
}

// ============================ prep kernels =================================
__global__ void split_kernel(const float* __restrict__ x,
                             __nv_bfloat16* __restrict__ hi,
                             __nv_bfloat16* __restrict__ lo, int n4)
{
    int idx = blockIdx.x * blockDim.x + threadIdx.x;
    if (idx >= n4) return;
    float4 v = ((const float4*)x)[idx];
    __nv_bfloat16 h0 = __float2bfloat16(v.x), h1 = __float2bfloat16(v.y);
    __nv_bfloat16 h2 = __float2bfloat16(v.z), h3 = __float2bfloat16(v.w);
    __nv_bfloat16 l0 = __float2bfloat16(v.x - __bfloat162float(h0));
    __nv_bfloat16 l1 = __float2bfloat16(v.y - __bfloat162float(h1));
    __nv_bfloat16 l2 = __float2bfloat16(v.z - __bfloat162float(h2));
    __nv_bfloat16 l3 = __float2bfloat16(v.w - __bfloat162float(h3));
    __nv_bfloat162* hp = (__nv_bfloat162*)hi;
    __nv_bfloat162* lp = (__nv_bfloat162*)lo;
    hp[idx * 2 + 0] = __nv_bfloat162(h0, h1);
    hp[idx * 2 + 1] = __nv_bfloat162(h2, h3);
    lp[idx * 2 + 0] = __nv_bfloat162(l0, l1);
    lp[idx * 2 + 1] = __nv_bfloat162(l2, l3);
}

__global__ void transpose_split_kernel(const float* __restrict__ W,
                                       __nv_bfloat16* __restrict__ hi,
                                       __nv_bfloat16* __restrict__ lo,
                                       int K, int N)
{
    __shared__ float t[32][33];
    int n0 = blockIdx.x * 32, k0 = blockIdx.y * 32;
    int tx = threadIdx.x, ty = threadIdx.y;   // 32 x 8
#pragma unroll
    for (int j = 0; j < 32; j += 8)
        t[ty + j][tx] = W[(size_t)(k0 + ty + j) * N + n0 + tx];
    __syncthreads();
#pragma unroll
    for (int j = 0; j < 32; j += 8) {
        float v = t[tx][ty + j];
        __nv_bfloat16 h = __float2bfloat16(v);
        __nv_bfloat16 l = __float2bfloat16(v - __bfloat162float(h));
        size_t o = (size_t)(n0 + ty + j) * K + k0 + tx;
        hi[o] = h;
        lo[o] = l;
    }
}

// ============================ HMMA GEMM ====================================
// C[M,N] = (Ahi+Alo)[M,K] @ (Bhi+Blo)^T, B stored [N][K] K-major, fp32 acc.
// bf16x3 via mma.sync.m16n8k16. BM=BN=128, BK=32, 256 threads,
// warps 2(M)x4(N), per-warp 64x32 (4x4 m16n8 tiles).
// 2-stage cp.async.ca double buffer (L1-allocating: adjacent CTAs share the A
// tile via L1 — .cg bypassed L1 and regressed in R8; this is the R9 fix).
// Rows padded to 80B (conflict-free ldmatrix phases, verified all 32 banks).
// Operand reuse: A_hi shared by hh/hl, B_hi shared by hh/lh (12 LDSM.x4/step).
// EPI=0: C row-major stride HID. EPI=1: scatter into g_qkv head-major.
#define BK 32
#define KT_STEPS (KDIM / BK)     // 128
#define ROWB 80                  // bytes per padded row (32 bf16 + 16B pad)
#define ARR  (128 * ROWB)        // 10240
#define STAGE (4 * ARR)          // 40960
#define GEMM_SMEM (2 * STAGE)    // 81920

template<int EPI>
__global__ void __launch_bounds__(256, 2)
hmma_gemm_kernel(const __nv_bfloat16* __restrict__ Ahi,
                 const __nv_bfloat16* __restrict__ Alo,
                 const __nv_bfloat16* __restrict__ Bhi,
                 const __nv_bfloat16* __restrict__ Blo,
                 float* __restrict__ C)
{
    extern __shared__ __align__(16) char smem[];
    const uint32_t sbase = smem_to_u32(smem);

    const int tid  = threadIdx.x;
    const int lane = tid & 31;
    const int wid  = tid >> 5;
    const int wm   = wid >> 2;        // 0..1  (M)
    const int wn   = wid & 3;         // 0..3  (N)
    const int bm   = blockIdx.y * 128;
    const int bn   = blockIdx.x * 128;

    const __nv_bfloat16* garr[4] = {Ahi, Alo, Bhi, Blo};

    // per-lane ldmatrix offsets (bytes)
    const uint32_t a_lane = (uint32_t)(lane & 15) * ROWB + (uint32_t)(lane >> 4) * 16;
    const uint32_t b_row  = (uint32_t)((lane & 7) | ((lane >> 4) << 3));
    const uint32_t b_lane = b_row * ROWB + (uint32_t)((lane >> 3) & 1) * 16;

    // cp.async: 2048 16B-chunks per stage, 8 per thread (loop-invariant decode)
    const __nv_bfloat16* csrc[8];
    uint32_t cdst[8];
#pragma unroll
    for (int i = 0; i < 8; i++) {
        int id  = tid + i * 256;
        int arr = id >> 9;             // 512 chunks per array
        int rem = id & 511;
        int row = rem >> 2;
        int c   = rem & 3;             // 16B chunk within 64B row
        int rbase = (arr < 2) ? bm : bn;
        csrc[i] = garr[arr] + ((size_t)(rbase + row) * KDIM + c * 8);
        cdst[i] = (uint32_t)(arr * ARR + row * ROWB + c * 16);
    }

    auto load_stage = [&](int stage, int k0) {
        uint32_t sb = sbase + stage * STAGE;
#pragma unroll
        for (int i = 0; i < 8; i++) {
            const void* gp = csrc[i] + k0;
            asm volatile("cp.async.ca.shared.global [%0], [%1], 16;"
                         :: "r"(sb + cdst[i]), "l"(gp));
        }
        asm volatile("cp.async.commit_group;" ::: "memory");
    };

    float acc[4][4][4];
#pragma unroll
    for (int i = 0; i < 4; i++)
#pragma unroll
        for (int j = 0; j < 4; j++)
#pragma unroll
            for (int r = 0; r < 4; r++) acc[i][j][r] = 0.f;

    load_stage(0, 0);

    for (int kt = 0; kt < KT_STEPS; kt++) {
        if (kt + 1 < KT_STEPS) {
            load_stage((kt + 1) & 1, (kt + 1) * BK);
            asm volatile("cp.async.wait_group 1;" ::: "memory");
        } else {
            asm volatile("cp.async.wait_group 0;" ::: "memory");
        }
        __syncthreads();

        const uint32_t buf = sbase + (kt & 1) * STAGE;
#pragma unroll
        for (int ks = 0; ks < 2; ks++) {
            const uint32_t kb = (uint32_t)ks * 32;   // k16 step = 32 bytes

            uint32_t a[4][4], bh[2][4], bl[2][4];
            // A_hi
#pragma unroll
            for (int mt = 0; mt < 4; mt++)
                ldmatrix_x4(a[mt][0], a[mt][1], a[mt][2], a[mt][3],
                            buf + (uint32_t)(wm * 64 + mt * 16) * ROWB + kb + a_lane);
            // B_hi
#pragma unroll
            for (int n2 = 0; n2 < 2; n2++)
                ldmatrix_x4(bh[n2][0], bh[n2][1], bh[n2][2], bh[n2][3],
                            buf + 2u * ARR + (uint32_t)(wn * 32 + n2 * 16) * ROWB + kb + b_lane);
            // B_lo
#pragma unroll
            for (int n2 = 0; n2 < 2; n2++)
                ldmatrix_x4(bl[n2][0], bl[n2][1], bl[n2][2], bl[n2][3],
                            buf + 3u * ARR + (uint32_t)(wn * 32 + n2 * 16) * ROWB + kb + b_lane);

            // hh + hl (A_hi against both B halves)
#pragma unroll
            for (int mt = 0; mt < 4; mt++)
#pragma unroll
                for (int nt = 0; nt < 4; nt++) {
                    mma_bf16(acc[mt][nt], a[mt],
                             bh[nt >> 1][(nt & 1) * 2], bh[nt >> 1][(nt & 1) * 2 + 1]);
                    mma_bf16(acc[mt][nt], a[mt],
                             bl[nt >> 1][(nt & 1) * 2], bl[nt >> 1][(nt & 1) * 2 + 1]);
                }

            // A_lo (overwrite a), lh
#pragma unroll
            for (int mt = 0; mt < 4; mt++)
                ldmatrix_x4(a[mt][0], a[mt][1], a[mt][2], a[mt][3],
                            buf + ARR + (uint32_t)(wm * 64 + mt * 16) * ROWB + kb + a_lane);
#pragma unroll
            for (int mt = 0; mt < 4; mt++)
#pragma unroll
                for (int nt = 0; nt < 4; nt++)
                    mma_bf16(acc[mt][nt], a[mt],
                             bh[nt >> 1][(nt & 1) * 2], bh[nt >> 1][(nt & 1) * 2 + 1]);
        }
        __syncthreads();
    }

    // ---- epilogue ----
#pragma unroll
    for (int mt = 0; mt < 4; mt++) {
#pragma unroll
        for (int half = 0; half < 2; half++) {
            int row = bm + wm * 64 + mt * 16 + (lane >> 2) + half * 8;
#pragma unroll
            for (int nt = 0; nt < 4; nt++) {
                int col = bn + wn * 32 + nt * 8 + (lane & 3) * 2;
                float v0 = acc[mt][nt][half * 2 + 0];
                float v1 = acc[mt][nt][half * 2 + 1];
                if (EPI == 0) {
                    C[(size_t)row * HID + col]     = v0;
                    C[(size_t)row * HID + col + 1] = v1;
                } else {
                    int b = row >> 10, s = row & 1023;
                    int part = col >> 12;
                    int rem  = col & 4095;
                    int h    = rem >> 7;
                    int d    = rem & 127;
                    size_t idx = ((((size_t)(part * BATCH + b) * NHEAD + h) * SEQ + s) * HDIM) + d;
                    C[idx]     = v0;
                    C[idx + 1] = v1;
                }
            }
        }
    }
}

// ============================ RoPE =========================================
__global__ void rope_kernel(float* __restrict__ qkv)
{
    int s  = blockIdx.x;
    int pb = blockIdx.y;
    int part = pb >> 7;
    int bh   = pb & 127;
    int b    = bh >> 5;
    int h    = bh & 31;
    int d    = threadIdx.x;

    float p = (float)s;
    float e = (float)(2 * d) * (1.0f / 128.0f);
    float inv_freq = 1.0f / powf(10000.0f, e);
    float freq = p * inv_freq;
    float c = cosf(freq);
    float sn = sinf(freq);

    size_t base = ((((size_t)(part * BATCH + b) * NHEAD + h) * SEQ + s) * HDIM);
    float x1 = qkv[base + d];
    float x2 = qkv[base + d + 64];
    qkv[base + d]      = x1 * c - x2 * sn;
    qkv[base + d + 64] = x2 * c + x1 * sn;
}

// ============================ flash attention (fp32) =======================
__global__ void __launch_bounds__(256)
attn_kernel(const float* __restrict__ Q, const float* __restrict__ K,
            const float* __restrict__ V, const float* __restrict__ mask,
            __nv_bfloat16* __restrict__ out_hi, __nv_bfloat16* __restrict__ out_lo)
{
    extern __shared__ float sm[];
    float* Qt = sm;
    float* Kt = Qt + 128 * 64;
    float* Vs = Kt + 128 * 64;
    float* Ps = Vs + 64 * 128;

    const int tid = threadIdx.x;
    const int tx  = tid & 15;
    const int ty  = tid >> 4;
    const int qt  = blockIdx.x;
    const int bh  = blockIdx.y;
    const int b   = bh >> 5;
    const int h   = bh & 31;
    const int q0  = qt * 64;

    const size_t head_off = (size_t)bh * SEQ * HDIM;
    const float* Qh = Q + head_off;
    const float* Kh = K + head_off;
    const float* Vh = V + head_off;

    for (int i = tid; i < 64 * 32; i += 256) {
        int m  = i >> 5;
        int d4 = (i & 31) << 2;
        float4 v = *(const float4*)(Qh + (size_t)(q0 + m) * HDIM + d4);
        Qt[(d4 + 0) * 64 + m] = v.x;
        Qt[(d4 + 1) * 64 + m] = v.y;
        Qt[(d4 + 2) * 64 + m] = v.z;
        Qt[(d4 + 3) * 64 + m] = v.w;
    }

    float m_i[4], l_i[4], o[4][8];
#pragma unroll
    for (int i = 0; i < 4; i++) {
        m_i[i] = -1e30f;
        l_i[i] = 0.f;
#pragma unroll
        for (int u = 0; u < 8; u++) o[i][u] = 0.f;
    }

    const float scale = 0.08838834764831845f;

    for (int kt = 0; kt <= qt; kt++) {
        const int k0 = kt * 64;
        __syncthreads();
        for (int i = tid; i < 64 * 32; i += 256) {
            int m  = i >> 5;
            int d4 = (i & 31) << 2;
            float4 v = *(const float4*)(Kh + (size_t)(k0 + m) * HDIM + d4);
            Kt[(d4 + 0) * 64 + m] = v.x;
            Kt[(d4 + 1) * 64 + m] = v.y;
            Kt[(d4 + 2) * 64 + m] = v.z;
            Kt[(d4 + 3) * 64 + m] = v.w;
            float4 w = *(const float4*)(Vh + (size_t)(k0 + m) * HDIM + d4);
            *(float4*)(Vs + m * 128 + d4) = w;
        }
        __syncthreads();

        float s[4][4];
#pragma unroll
        for (int i = 0; i < 4; i++)
#pragma unroll
            for (int j = 0; j < 4; j++) s[i][j] = 0.f;

#pragma unroll 4
        for (int kk = 0; kk < 128; kk++) {
            float4 qa = *(float4*)(Qt + kk * 64 + 4 * ty);
            float4 kb = *(float4*)(Kt + kk * 64 + 4 * tx);
            float a[4] = {qa.x, qa.y, qa.z, qa.w};
            float bb[4] = {kb.x, kb.y, kb.z, kb.w};
#pragma unroll
            for (int i = 0; i < 4; i++)
#pragma unroll
                for (int j = 0; j < 4; j++)
                    s[i][j] = fmaf(a[i], bb[j], s[i][j]);
        }

        if (kt == qt) {
            const size_t mbase = (size_t)b * SEQ * SEQ;
#pragma unroll
            for (int i = 0; i < 4; i++) {
                int q = q0 + 4 * ty + i;
#pragma unroll
                for (int j = 0; j < 4; j++) {
                    int kcol = k0 + 4 * tx + j;
                    s[i][j] = s[i][j] * scale + mask[mbase + (size_t)q * SEQ + kcol];
                }
            }
        } else {
#pragma unroll
            for (int i = 0; i < 4; i++)
#pragma unroll
                for (int j = 0; j < 4; j++) s[i][j] *= scale;
        }

        float alpha[4];
#pragma unroll
        for (int i = 0; i < 4; i++) {
            float r = fmaxf(fmaxf(s[i][0], s[i][1]), fmaxf(s[i][2], s[i][3]));
#pragma unroll
            for (int off = 8; off > 0; off >>= 1)
                r = fmaxf(r, __shfl_xor_sync(0xffffffffu, r, off, 16));
            float mnew = fmaxf(m_i[i], r);
            alpha[i] = __expf(m_i[i] - mnew);
            float rs = 0.f;
#pragma unroll
            for (int j = 0; j < 4; j++) {
                s[i][j] = __expf(s[i][j] - mnew);
                rs += s[i][j];
            }
#pragma unroll
            for (int off = 8; off > 0; off >>= 1)
                rs += __shfl_xor_sync(0xffffffffu, rs, off, 16);
            l_i[i] = l_i[i] * alpha[i] + rs;
            m_i[i] = mnew;
        }

#pragma unroll
        for (int i = 0; i < 4; i++) {
            *(float4*)(Ps + (4 * ty + i) * 68 + 4 * tx) =
                make_float4(s[i][0], s[i][1], s[i][2], s[i][3]);
        }
        __syncthreads();

#pragma unroll
        for (int i = 0; i < 4; i++)
#pragma unroll
            for (int u = 0; u < 8; u++) o[i][u] *= alpha[i];

#pragma unroll 4
        for (int k = 0; k < 64; k++) {
            float pv[4];
#pragma unroll
            for (int i = 0; i < 4; i++) pv[i] = Ps[(4 * ty + i) * 68 + k];
#pragma unroll
            for (int u = 0; u < 8; u++) {
                float vv = Vs[k * 128 + tx + 16 * u];
#pragma unroll
                for (int i = 0; i < 4; i++)
                    o[i][u] = fmaf(pv[i], vv, o[i][u]);
            }
        }
    }

#pragma unroll
    for (int i = 0; i < 4; i++) {
        float inv_l = 1.f / l_i[i];
        int q = q0 + 4 * ty + i;
        size_t rowbase = ((size_t)b * SEQ + q) * HID + (size_t)h * HDIM;
#pragma unroll
        for (int u = 0; u < 8; u++) {
            float val = o[i][u] * inv_l;
            __nv_bfloat16 hv = __float2bfloat16(val);
            out_hi[rowbase + tx + 16 * u] = hv;
            out_lo[rowbase + tx + 16 * u] = __float2bfloat16(val - __bfloat162float(hv));
        }
    }
}

// ============================ launch =======================================
extern "C" void kernel_launch(void* const* d_in, const int* in_sizes, int n_in,
                              void* d_out, int out_size)
{
    const float* hidden = (const float*)d_in[0];
    const float* Wp     = (const float*)d_in[1];
    const float* Wo     = (const float*)d_in[2];
    const float* mask   = (const float*)d_in[3];
    float* out = (float*)d_out;

    float *qkv = nullptr;
    __nv_bfloat16 *a1hi, *a1lo, *bphi, *bplo, *bohi, *bolo, *athi, *atlo;
    cudaGetSymbolAddress((void**)&qkv,  g_qkv);
    cudaGetSymbolAddress((void**)&a1hi, g_a1hi);
    cudaGetSymbolAddress((void**)&a1lo, g_a1lo);
    cudaGetSymbolAddress((void**)&bphi, g_bphi);
    cudaGetSymbolAddress((void**)&bplo, g_bplo);
    cudaGetSymbolAddress((void**)&bohi, g_bohi);
    cudaGetSymbolAddress((void**)&bolo, g_bolo);
    cudaGetSymbolAddress((void**)&athi, g_athi);
    cudaGetSymbolAddress((void**)&atlo, g_atlo);

    // Prep: split hidden; transpose+split weights
    split_kernel<<<(M_ROWS * KDIM / 4 + 255) / 256, 256>>>(hidden, a1hi, a1lo, M_ROWS * KDIM / 4);
    transpose_split_kernel<<<dim3(QKV_N / 32, KDIM / 32), dim3(32, 8)>>>(Wp, bphi, bplo, KDIM, QKV_N);
    transpose_split_kernel<<<dim3(HID  / 32, KDIM / 32), dim3(32, 8)>>>(Wo, bohi, bolo, KDIM, HID);

    cudaFuncSetAttribute(hmma_gemm_kernel<0>, cudaFuncAttributeMaxDynamicSharedMemorySize, GEMM_SMEM);
    cudaFuncSetAttribute(hmma_gemm_kernel<1>, cudaFuncAttributeMaxDynamicSharedMemorySize, GEMM_SMEM);

    // GEMM1: QKV projection -> g_qkv head-major fp32
    hmma_gemm_kernel<1><<<dim3(QKV_N / 128, M_ROWS / 128), 256, GEMM_SMEM>>>(
        a1hi, a1lo, bphi, bplo, qkv);

    // RoPE
    rope_kernel<<<dim3(SEQ, 2 * BATCH * NHEAD), 64>>>(qkv);

    // Flash attention -> bf16 hi/lo
    const float* Qp = qkv;
    const float* Kp = qkv + (size_t)HEAD_ELEMS;
    const float* Vp = qkv + 2ull * HEAD_ELEMS;
    int attn_smem = (128 * 64 + 128 * 64 + 64 * 128 + 64 * 68) * (int)sizeof(float);
    cudaFuncSetAttribute(attn_kernel, cudaFuncAttributeMaxDynamicSharedMemorySize, attn_smem);
    attn_kernel<<<dim3(SEQ / 64, BATCH * NHEAD), 256, attn_smem>>>(
        Qp, Kp, Vp, mask, athi, atlo);

    // GEMM2: output projection
    hmma_gemm_kernel<0><<<dim3(HID / 128, M_ROWS / 128), 256, GEMM_SMEM>>>(
        athi, atlo, bohi, bolo, out);
}

// round 10
// speedup vs baseline: 1.0418x; 1.0418x over previous
#include <cuda_runtime.h>
#include <cuda_bf16.h>
#include <cstdint>

// ============================ problem constants ============================
#define BATCH 4
#define SEQ   1024
#define HID   4096
#define NHEAD 32
#define HDIM  128
#define M_ROWS (BATCH*SEQ)          // 4096
#define QKV_N  (3*HID)              // 12288
#define KDIM   4096
#define HEAD_ELEMS (BATCH*NHEAD*SEQ*HDIM)  // 16,777,216 per part

// ============================ scratch (device globals) =====================
__device__ float g_qkv[3ull * HEAD_ELEMS];                 // [part][b][h][s][d] fp32
__device__ __nv_bfloat16 g_a1hi[(size_t)M_ROWS * KDIM];    // hidden split  [m][k]
__device__ __nv_bfloat16 g_a1lo[(size_t)M_ROWS * KDIM];
__device__ __nv_bfloat16 g_bphi[(size_t)QKV_N * KDIM];     // W_pack^T split [n][k]
__device__ __nv_bfloat16 g_bplo[(size_t)QKV_N * KDIM];
__device__ __nv_bfloat16 g_bohi[(size_t)HID * KDIM];       // W_o^T split [n][k]
__device__ __nv_bfloat16 g_bolo[(size_t)HID * KDIM];
__device__ __nv_bfloat16 g_athi[(size_t)M_ROWS * HID];     // attn out split [m][k]
__device__ __nv_bfloat16 g_atlo[(size_t)M_ROWS * HID];

// ============================ helpers ======================================
__device__ __forceinline__ uint32_t smem_to_u32(const void* p) {
    uint32_t a;
    asm("{ .reg .u64 t; cvta.to.shared.u64 t, %1; cvt.u32.u64 %0, t; }" : "=r"(a) : "l"(p));
    return a;
}

__device__ __forceinline__ void ldmatrix_x4(uint32_t& r0, uint32_t& r1,
                                            uint32_t& r2, uint32_t& r3, uint32_t addr) {
    asm volatile("ldmatrix.sync.aligned.m8n8.x4.shared.b16 {%0,%1,%2,%3}, [%4];"
                 : "=r"(r0), "=r"(r1), "=r"(r2), "=r"(r3) : "r"(addr));
}

__device__ __forceinline__ void mma_bf16(float* d, const uint32_t* a, uint32_t b0, uint32_t b1) {
    asm volatile(
        "mma.sync.aligned.m16n8k16.row.col.f32.bf16.bf16.f32 "
        "{%0,%1,%2,%3}, {%4,%5,%6,%7}, {%8,%9}, {%0,%1,%2,%3};"
        : "+f"(d[0]), "+f"(d[1]), "+f"(d[2]), "+f"(d[3])
        : "r"(a[0]), "r"(a[1]), "r"(a[2]), "r"(a[3]), "r"(b0), "r"(b1));
}

// ============================ prep kernels =================================
__global__ void split_kernel(const float* __restrict__ x,
                             __nv_bfloat16* __restrict__ hi,
                             __nv_bfloat16* __restrict__ lo, int n4)
{
    int idx = blockIdx.x * blockDim.x + threadIdx.x;
    if (idx >= n4) return;
    float4 v = ((const float4*)x)[idx];
    __nv_bfloat16 h0 = __float2bfloat16(v.x), h1 = __float2bfloat16(v.y);
    __nv_bfloat16 h2 = __float2bfloat16(v.z), h3 = __float2bfloat16(v.w);
    __nv_bfloat16 l0 = __float2bfloat16(v.x - __bfloat162float(h0));
    __nv_bfloat16 l1 = __float2bfloat16(v.y - __bfloat162float(h1));
    __nv_bfloat16 l2 = __float2bfloat16(v.z - __bfloat162float(h2));
    __nv_bfloat16 l3 = __float2bfloat16(v.w - __bfloat162float(h3));
    __nv_bfloat162* hp = (__nv_bfloat162*)hi;
    __nv_bfloat162* lp = (__nv_bfloat162*)lo;
    hp[idx * 2 + 0] = __nv_bfloat162(h0, h1);
    hp[idx * 2 + 1] = __nv_bfloat162(h2, h3);
    lp[idx * 2 + 0] = __nv_bfloat162(l0, l1);
    lp[idx * 2 + 1] = __nv_bfloat162(l2, l3);
}

__global__ void transpose_split_kernel(const float* __restrict__ W,
                                       __nv_bfloat16* __restrict__ hi,
                                       __nv_bfloat16* __restrict__ lo,
                                       int K, int N)
{
    __shared__ float t[32][33];
    int n0 = blockIdx.x * 32, k0 = blockIdx.y * 32;
    int tx = threadIdx.x, ty = threadIdx.y;   // 32 x 8
#pragma unroll
    for (int j = 0; j < 32; j += 8)
        t[ty + j][tx] = W[(size_t)(k0 + ty + j) * N + n0 + tx];
    __syncthreads();
#pragma unroll
    for (int j = 0; j < 32; j += 8) {
        float v = t[tx][ty + j];
        __nv_bfloat16 h = __float2bfloat16(v);
        __nv_bfloat16 l = __float2bfloat16(v - __bfloat162float(h));
        size_t o = (size_t)(n0 + ty + j) * K + k0 + tx;
        hi[o] = h;
        lo[o] = l;
    }
}

// ============================ HMMA GEMM ====================================
// C[M,N] = (Ahi+Alo)[M,K] @ (Bhi+Blo)^T, B stored [N][K] K-major, fp32 acc.
// bf16x3 via mma.sync.m16n8k16. BM=BN=128, BK=64, 256 threads,
// warps 2(M)x4(N), per-warp 64x32 (4x4 m16n8 tiles).
// R7 loader (LDG+STS, single buffer, 144B rows) + reuse-ordered compute:
// A_hi shared by hh/hl, B_hi shared by hh/lh -> 12 LDSM.x4 per k16-step.
// EPI=0: C row-major stride HID. EPI=1: scatter into g_qkv head-major.
#define BK 64
#define KT_STEPS (KDIM / BK)     // 64
#define ARR 18432                // 128 * 144 bytes
#define GEMM_SMEM (4 * ARR)      // 73728

template<int EPI>
__global__ void __launch_bounds__(256, 2)
hmma_gemm_kernel(const __nv_bfloat16* __restrict__ Ahi,
                 const __nv_bfloat16* __restrict__ Alo,
                 const __nv_bfloat16* __restrict__ Bhi,
                 const __nv_bfloat16* __restrict__ Blo,
                 float* __restrict__ C)
{
    extern __shared__ __align__(16) char smem[];
    const uint32_t sbase = smem_to_u32(smem);

    const int tid  = threadIdx.x;
    const int lane = tid & 31;
    const int wid  = tid >> 5;
    const int wm   = wid >> 2;        // 0..1  (M)
    const int wn   = wid & 3;         // 0..3  (N)
    const int bm   = blockIdx.y * 128;
    const int bn   = blockIdx.x * 128;

    const __nv_bfloat16* garr[4] = {Ahi, Alo, Bhi, Blo};

    // per-lane ldmatrix offsets (bytes)
    const uint32_t a_lane = (uint32_t)(lane & 15) * 144 + (uint32_t)(lane >> 4) * 16;
    const uint32_t b_row  = (uint32_t)((lane & 7) | ((lane >> 4) << 3));
    const uint32_t b_lane = b_row * 144 + (uint32_t)((lane >> 3) & 1) * 16;

    float acc[4][4][4];
#pragma unroll
    for (int i = 0; i < 4; i++)
#pragma unroll
        for (int j = 0; j < 4; j++)
#pragma unroll
            for (int r = 0; r < 4; r++) acc[i][j][r] = 0.f;

    for (int kt = 0; kt < KT_STEPS; kt++) {
        const int k0 = kt * BK;
        __syncthreads();
        // ---- load 4 arrays x [128 rows x 64 bf16] into padded smem ----
#pragma unroll
        for (int i = 0; i < 16; i++) {
            int arr  = i >> 2;
            int rem  = ((i & 3) << 8) + tid;     // 0..1023
            int row  = rem >> 3;
            int part = rem & 7;
            int rbase = (arr < 2) ? bm : bn;
            const uint4* gp = (const uint4*)(garr[arr] + ((size_t)(rbase + row) * KDIM + k0 + part * 8));
            uint4 v = *gp;
            *(uint4*)(smem + arr * ARR + row * 144 + part * 16) = v;
        }
        __syncthreads();

        // ---- compute: 4 k16 steps, reuse-ordered (12 LDSM.x4 per step) ----
#pragma unroll
        for (int ks = 0; ks < 4; ks++) {
            const uint32_t kb = (uint32_t)ks * 32;

            uint32_t a[4][4], bh[2][4], bl[2][4];
            // A_hi
#pragma unroll
            for (int mt = 0; mt < 4; mt++)
                ldmatrix_x4(a[mt][0], a[mt][1], a[mt][2], a[mt][3],
                            sbase + (uint32_t)(wm * 64 + mt * 16) * 144 + kb + a_lane);
            // B_hi
#pragma unroll
            for (int n2 = 0; n2 < 2; n2++)
                ldmatrix_x4(bh[n2][0], bh[n2][1], bh[n2][2], bh[n2][3],
                            sbase + 2u * ARR + (uint32_t)(wn * 32 + n2 * 16) * 144 + kb + b_lane);
            // B_lo
#pragma unroll
            for (int n2 = 0; n2 < 2; n2++)
                ldmatrix_x4(bl[n2][0], bl[n2][1], bl[n2][2], bl[n2][3],
                            sbase + 3u * ARR + (uint32_t)(wn * 32 + n2 * 16) * 144 + kb + b_lane);

            // hh + hl (A_hi against both B halves)
#pragma unroll
            for (int mt = 0; mt < 4; mt++)
#pragma unroll
                for (int nt = 0; nt < 4; nt++) {
                    mma_bf16(acc[mt][nt], a[mt],
                             bh[nt >> 1][(nt & 1) * 2], bh[nt >> 1][(nt & 1) * 2 + 1]);
                    mma_bf16(acc[mt][nt], a[mt],
                             bl[nt >> 1][(nt & 1) * 2], bl[nt >> 1][(nt & 1) * 2 + 1]);
                }

            // A_lo (overwrite a), lh
#pragma unroll
            for (int mt = 0; mt < 4; mt++)
                ldmatrix_x4(a[mt][0], a[mt][1], a[mt][2], a[mt][3],
                            sbase + ARR + (uint32_t)(wm * 64 + mt * 16) * 144 + kb + a_lane);
#pragma unroll
            for (int mt = 0; mt < 4; mt++)
#pragma unroll
                for (int nt = 0; nt < 4; nt++)
                    mma_bf16(acc[mt][nt], a[mt],
                             bh[nt >> 1][(nt & 1) * 2], bh[nt >> 1][(nt & 1) * 2 + 1]);
        }
    }

    // ---- epilogue ----
#pragma unroll
    for (int mt = 0; mt < 4; mt++) {
#pragma unroll
        for (int half = 0; half < 2; half++) {
            int row = bm + wm * 64 + mt * 16 + (lane >> 2) + half * 8;
#pragma unroll
            for (int nt = 0; nt < 4; nt++) {
                int col = bn + wn * 32 + nt * 8 + (lane & 3) * 2;
                float v0 = acc[mt][nt][half * 2 + 0];
                float v1 = acc[mt][nt][half * 2 + 1];
                if (EPI == 0) {
                    C[(size_t)row * HID + col]     = v0;
                    C[(size_t)row * HID + col + 1] = v1;
                } else {
                    int b = row >> 10, s = row & 1023;
                    int part = col >> 12;
                    int rem  = col & 4095;
                    int h    = rem >> 7;
                    int d    = rem & 127;
                    size_t idx = ((((size_t)(part * BATCH + b) * NHEAD + h) * SEQ + s) * HDIM) + d;
                    C[idx]     = v0;
                    C[idx + 1] = v1;
                }
            }
        }
    }
}

// ============================ RoPE =========================================
__global__ void rope_kernel(float* __restrict__ qkv)
{
    int s  = blockIdx.x;
    int pb = blockIdx.y;
    int part = pb >> 7;
    int bh   = pb & 127;
    int b    = bh >> 5;
    int h    = bh & 31;
    int d    = threadIdx.x;

    float p = (float)s;
    float e = (float)(2 * d) * (1.0f / 128.0f);
    float inv_freq = 1.0f / powf(10000.0f, e);
    float freq = p * inv_freq;
    float c = cosf(freq);
    float sn = sinf(freq);

    size_t base = ((((size_t)(part * BATCH + b) * NHEAD + h) * SEQ + s) * HDIM);
    float x1 = qkv[base + d];
    float x2 = qkv[base + d + 64];
    qkv[base + d]      = x1 * c - x2 * sn;
    qkv[base + d + 64] = x2 * c + x1 * sn;
}

// ============================ flash attention (fp32) =======================
__global__ void __launch_bounds__(256)
attn_kernel(const float* __restrict__ Q, const float* __restrict__ K,
            const float* __restrict__ V, const float* __restrict__ mask,
            __nv_bfloat16* __restrict__ out_hi, __nv_bfloat16* __restrict__ out_lo)
{
    extern __shared__ float sm[];
    float* Qt = sm;
    float* Kt = Qt + 128 * 64;
    float* Vs = Kt + 128 * 64;
    float* Ps = Vs + 64 * 128;

    const int tid = threadIdx.x;
    const int tx  = tid & 15;
    const int ty  = tid >> 4;
    const int qt  = blockIdx.x;
    const int bh  = blockIdx.y;
    const int b   = bh >> 5;
    const int h   = bh & 31;
    const int q0  = qt * 64;

    const size_t head_off = (size_t)bh * SEQ * HDIM;
    const float* Qh = Q + head_off;
    const float* Kh = K + head_off;
    const float* Vh = V + head_off;

    for (int i = tid; i < 64 * 32; i += 256) {
        int m  = i >> 5;
        int d4 = (i & 31) << 2;
        float4 v = *(const float4*)(Qh + (size_t)(q0 + m) * HDIM + d4);
        Qt[(d4 + 0) * 64 + m] = v.x;
        Qt[(d4 + 1) * 64 + m] = v.y;
        Qt[(d4 + 2) * 64 + m] = v.z;
        Qt[(d4 + 3) * 64 + m] = v.w;
    }

    float m_i[4], l_i[4], o[4][8];
#pragma unroll
    for (int i = 0; i < 4; i++) {
        m_i[i] = -1e30f;
        l_i[i] = 0.f;
#pragma unroll
        for (int u = 0; u < 8; u++) o[i][u] = 0.f;
    }

    const float scale = 0.08838834764831845f;

    for (int kt = 0; kt <= qt; kt++) {
        const int k0 = kt * 64;
        __syncthreads();
        for (int i = tid; i < 64 * 32; i += 256) {
            int m  = i >> 5;
            int d4 = (i & 31) << 2;
            float4 v = *(const float4*)(Kh + (size_t)(k0 + m) * HDIM + d4);
            Kt[(d4 + 0) * 64 + m] = v.x;
            Kt[(d4 + 1) * 64 + m] = v.y;
            Kt[(d4 + 2) * 64 + m] = v.z;
            Kt[(d4 + 3) * 64 + m] = v.w;
            float4 w = *(const float4*)(Vh + (size_t)(k0 + m) * HDIM + d4);
            *(float4*)(Vs + m * 128 + d4) = w;
        }
        __syncthreads();

        float s[4][4];
#pragma unroll
        for (int i = 0; i < 4; i++)
#pragma unroll
            for (int j = 0; j < 4; j++) s[i][j] = 0.f;

#pragma unroll 4
        for (int kk = 0; kk < 128; kk++) {
            float4 qa = *(float4*)(Qt + kk * 64 + 4 * ty);
            float4 kb = *(float4*)(Kt + kk * 64 + 4 * tx);
            float a[4] = {qa.x, qa.y, qa.z, qa.w};
            float bb[4] = {kb.x, kb.y, kb.z, kb.w};
#pragma unroll
            for (int i = 0; i < 4; i++)
#pragma unroll
                for (int j = 0; j < 4; j++)
                    s[i][j] = fmaf(a[i], bb[j], s[i][j]);
        }

        if (kt == qt) {
            const size_t mbase = (size_t)b * SEQ * SEQ;
#pragma unroll
            for (int i = 0; i < 4; i++) {
                int q = q0 + 4 * ty + i;
#pragma unroll
                for (int j = 0; j < 4; j++) {
                    int kcol = k0 + 4 * tx + j;
                    s[i][j] = s[i][j] * scale + mask[mbase + (size_t)q * SEQ + kcol];
                }
            }
        } else {
#pragma unroll
            for (int i = 0; i < 4; i++)
#pragma unroll
                for (int j = 0; j < 4; j++) s[i][j] *= scale;
        }

        float alpha[4];
#pragma unroll
        for (int i = 0; i < 4; i++) {
            float r = fmaxf(fmaxf(s[i][0], s[i][1]), fmaxf(s[i][2], s[i][3]));
#pragma unroll
            for (int off = 8; off > 0; off >>= 1)
                r = fmaxf(r, __shfl_xor_sync(0xffffffffu, r, off, 16));
            float mnew = fmaxf(m_i[i], r);
            alpha[i] = __expf(m_i[i] - mnew);
            float rs = 0.f;
#pragma unroll
            for (int j = 0; j < 4; j++) {
                s[i][j] = __expf(s[i][j] - mnew);
                rs += s[i][j];
            }
#pragma unroll
            for (int off = 8; off > 0; off >>= 1)
                rs += __shfl_xor_sync(0xffffffffu, rs, off, 16);
            l_i[i] = l_i[i] * alpha[i] + rs;
            m_i[i] = mnew;
        }

#pragma unroll
        for (int i = 0; i < 4; i++) {
            *(float4*)(Ps + (4 * ty + i) * 68 + 4 * tx) =
                make_float4(s[i][0], s[i][1], s[i][2], s[i][3]);
        }
        __syncthreads();

#pragma unroll
        for (int i = 0; i < 4; i++)
#pragma unroll
            for (int u = 0; u < 8; u++) o[i][u] *= alpha[i];

#pragma unroll 4
        for (int k = 0; k < 64; k++) {
            float pv[4];
#pragma unroll
            for (int i = 0; i < 4; i++) pv[i] = Ps[(4 * ty + i) * 68 + k];
#pragma unroll
            for (int u = 0; u < 8; u++) {
                float vv = Vs[k * 128 + tx + 16 * u];
#pragma unroll
                for (int i = 0; i < 4; i++)
                    o[i][u] = fmaf(pv[i], vv, o[i][u]);
            }
        }
    }

#pragma unroll
    for (int i = 0; i < 4; i++) {
        float inv_l = 1.f / l_i[i];
        int q = q0 + 4 * ty + i;
        size_t rowbase = ((size_t)b * SEQ + q) * HID + (size_t)h * HDIM;
#pragma unroll
        for (int u = 0; u < 8; u++) {
            float val = o[i][u] * inv_l;
            __nv_bfloat16 hv = __float2bfloat16(val);
            out_hi[rowbase + tx + 16 * u] = hv;
            out_lo[rowbase + tx + 16 * u] = __float2bfloat16(val - __bfloat162float(hv));
        }
    }
}

// ============================ launch =======================================
extern "C" void kernel_launch(void* const* d_in, const int* in_sizes, int n_in,
                              void* d_out, int out_size)
{
    const float* hidden = (const float*)d_in[0];
    const float* Wp     = (const float*)d_in[1];
    const float* Wo     = (const float*)d_in[2];
    const float* mask   = (const float*)d_in[3];
    float* out = (float*)d_out;

    float *qkv = nullptr;
    __nv_bfloat16 *a1hi, *a1lo, *bphi, *bplo, *bohi, *bolo, *athi, *atlo;
    cudaGetSymbolAddress((void**)&qkv,  g_qkv);
    cudaGetSymbolAddress((void**)&a1hi, g_a1hi);
    cudaGetSymbolAddress((void**)&a1lo, g_a1lo);
    cudaGetSymbolAddress((void**)&bphi, g_bphi);
    cudaGetSymbolAddress((void**)&bplo, g_bplo);
    cudaGetSymbolAddress((void**)&bohi, g_bohi);
    cudaGetSymbolAddress((void**)&bolo, g_bolo);
    cudaGetSymbolAddress((void**)&athi, g_athi);
    cudaGetSymbolAddress((void**)&atlo, g_atlo);

    // Prep: split hidden; transpose+split weights
    split_kernel<<<(M_ROWS * KDIM / 4 + 255) / 256, 256>>>(hidden, a1hi, a1lo, M_ROWS * KDIM / 4);
    transpose_split_kernel<<<dim3(QKV_N / 32, KDIM / 32), dim3(32, 8)>>>(Wp, bphi, bplo, KDIM, QKV_N);
    transpose_split_kernel<<<dim3(HID  / 32, KDIM / 32), dim3(32, 8)>>>(Wo, bohi, bolo, KDIM, HID);

    cudaFuncSetAttribute(hmma_gemm_kernel<0>, cudaFuncAttributeMaxDynamicSharedMemorySize, GEMM_SMEM);
    cudaFuncSetAttribute(hmma_gemm_kernel<1>, cudaFuncAttributeMaxDynamicSharedMemorySize, GEMM_SMEM);

    // GEMM1: QKV projection -> g_qkv head-major fp32
    hmma_gemm_kernel<1><<<dim3(QKV_N / 128, M_ROWS / 128), 256, GEMM_SMEM>>>(
        a1hi, a1lo, bphi, bplo, qkv);

    // RoPE
    rope_kernel<<<dim3(SEQ, 2 * BATCH * NHEAD), 64>>>(qkv);

    // Flash attention -> bf16 hi/lo
    const float* Qp = qkv;
    const float* Kp = qkv + (size_t)HEAD_ELEMS;
    const float* Vp = qkv + 2ull * HEAD_ELEMS;
    int attn_smem = (128 * 64 + 128 * 64 + 64 * 128 + 64 * 68) * (int)sizeof(float);
    cudaFuncSetAttribute(attn_kernel, cudaFuncAttributeMaxDynamicSharedMemorySize, attn_smem);
    attn_kernel<<<dim3(SEQ / 64, BATCH * NHEAD), 256, attn_smem>>>(
        Qp, Kp, Vp, mask, athi, atlo);

    // GEMM2: output projection
    hmma_gemm_kernel<0><<<dim3(HID / 128, M_ROWS / 128), 256, GEMM_SMEM>>>(
        athi, atlo, bohi, bolo, out);
}

// round 11
// speedup vs baseline: 1.0933x; 1.0494x over previous
#include <cuda_runtime.h>
#include <cuda_bf16.h>
#include <cstdint>

// ============================ problem constants ============================
#define BATCH 4
#define SEQ   1024
#define HID   4096
#define NHEAD 32
#define HDIM  128
#define M_ROWS (BATCH*SEQ)          // 4096
#define QKV_N  (3*HID)              // 12288
#define KDIM   4096
#define HEAD_ELEMS (BATCH*NHEAD*SEQ*HDIM)  // 16,777,216 per part

// ============================ scratch (device globals) =====================
__device__ float g_qkv[3ull * HEAD_ELEMS];                 // [part][b][h][s][d] fp32
__device__ __nv_bfloat16 g_a1hi[(size_t)M_ROWS * KDIM];
__device__ __nv_bfloat16 g_a1lo[(size_t)M_ROWS * KDIM];
__device__ __nv_bfloat16 g_bphi[(size_t)QKV_N * KDIM];
__device__ __nv_bfloat16 g_bplo[(size_t)QKV_N * KDIM];
__device__ __nv_bfloat16 g_bohi[(size_t)HID * KDIM];
__device__ __nv_bfloat16 g_bolo[(size_t)HID * KDIM];
__device__ __nv_bfloat16 g_athi[(size_t)M_ROWS * HID];
__device__ __nv_bfloat16 g_atlo[(size_t)M_ROWS * HID];
// attention operands (bf16 hi/lo)
__device__ __nv_bfloat16 g_qhi[(size_t)HEAD_ELEMS];        // [bh][s][d]
__device__ __nv_bfloat16 g_qlo[(size_t)HEAD_ELEMS];
__device__ __nv_bfloat16 g_khi[(size_t)HEAD_ELEMS];
__device__ __nv_bfloat16 g_klo[(size_t)HEAD_ELEMS];
__device__ __nv_bfloat16 g_vthi[(size_t)HEAD_ELEMS];       // [bh][d][s]
__device__ __nv_bfloat16 g_vtlo[(size_t)HEAD_ELEMS];

// ============================ helpers ======================================
__device__ __forceinline__ uint32_t smem_to_u32(const void* p) {
    uint32_t a;
    asm("{ .reg .u64 t; cvta.to.shared.u64 t, %1; cvt.u32.u64 %0, t; }" : "=r"(a) : "l"(p));
    return a;
}

__device__ __forceinline__ void ldmatrix_x4(uint32_t& r0, uint32_t& r1,
                                            uint32_t& r2, uint32_t& r3, uint32_t addr) {
    asm volatile("ldmatrix.sync.aligned.m8n8.x4.shared.b16 {%0,%1,%2,%3}, [%4];"
                 : "=r"(r0), "=r"(r1), "=r"(r2), "=r"(r3) : "r"(addr));
}

__device__ __forceinline__ void mma_bf16(float* d, const uint32_t* a, uint32_t b0, uint32_t b1) {
    asm volatile(
        "mma.sync.aligned.m16n8k16.row.col.f32.bf16.bf16.f32 "
        "{%0,%1,%2,%3}, {%4,%5,%6,%7}, {%8,%9}, {%0,%1,%2,%3};"
        : "+f"(d[0]), "+f"(d[1]), "+f"(d[2]), "+f"(d[3])
        : "r"(a[0]), "r"(a[1]), "r"(a[2]), "r"(a[3]), "r"(b0), "r"(b1));
}

__device__ __forceinline__ uint32_t pack_bf16x2(float x, float y) {
    __nv_bfloat162 t = __floats2bfloat162_rn(x, y);
    return *(uint32_t*)&t;
}
__device__ __forceinline__ float bf16_res(float x) {
    return x - __bfloat162float(__float2bfloat16(x));
}

// ============================ prep kernels =================================
__global__ void split_kernel(const float* __restrict__ x,
                             __nv_bfloat16* __restrict__ hi,
                             __nv_bfloat16* __restrict__ lo, int n4)
{
    int idx = blockIdx.x * blockDim.x + threadIdx.x;
    if (idx >= n4) return;
    float4 v = ((const float4*)x)[idx];
    __nv_bfloat16 h0 = __float2bfloat16(v.x), h1 = __float2bfloat16(v.y);
    __nv_bfloat16 h2 = __float2bfloat16(v.z), h3 = __float2bfloat16(v.w);
    __nv_bfloat16 l0 = __float2bfloat16(v.x - __bfloat162float(h0));
    __nv_bfloat16 l1 = __float2bfloat16(v.y - __bfloat162float(h1));
    __nv_bfloat16 l2 = __float2bfloat16(v.z - __bfloat162float(h2));
    __nv_bfloat16 l3 = __float2bfloat16(v.w - __bfloat162float(h3));
    __nv_bfloat162* hp = (__nv_bfloat162*)hi;
    __nv_bfloat162* lp = (__nv_bfloat162*)lo;
    hp[idx * 2 + 0] = __nv_bfloat162(h0, h1);
    hp[idx * 2 + 1] = __nv_bfloat162(h2, h3);
    lp[idx * 2 + 0] = __nv_bfloat162(l0, l1);
    lp[idx * 2 + 1] = __nv_bfloat162(l2, l3);
}

__global__ void transpose_split_kernel(const float* __restrict__ W,
                                       __nv_bfloat16* __restrict__ hi,
                                       __nv_bfloat16* __restrict__ lo,
                                       int K, int N)
{
    __shared__ float t[32][33];
    int n0 = blockIdx.x * 32, k0 = blockIdx.y * 32;
    int tx = threadIdx.x, ty = threadIdx.y;   // 32 x 8
#pragma unroll
    for (int j = 0; j < 32; j += 8)
        t[ty + j][tx] = W[(size_t)(k0 + ty + j) * N + n0 + tx];
    __syncthreads();
#pragma unroll
    for (int j = 0; j < 32; j += 8) {
        float v = t[tx][ty + j];
        __nv_bfloat16 h = __float2bfloat16(v);
        __nv_bfloat16 l = __float2bfloat16(v - __bfloat162float(h));
        size_t o = (size_t)(n0 + ty + j) * K + k0 + tx;
        hi[o] = h;
        lo[o] = l;
    }
}

// Per-head transpose+split of V: g_qkv part2 [bh][s][d] -> [bh][d][s] bf16 hi/lo
__global__ void vtrans_kernel(const float* __restrict__ V,
                              __nv_bfloat16* __restrict__ vthi,
                              __nv_bfloat16* __restrict__ vtlo)
{
    __shared__ float t[32][33];
    int d0 = blockIdx.x * 32, s0 = blockIdx.y * 32, bh = blockIdx.z;
    int tx = threadIdx.x, ty = threadIdx.y;   // 32 x 8
    const float* Vh = V + (size_t)bh * SEQ * HDIM;
#pragma unroll
    for (int j = 0; j < 32; j += 8)
        t[ty + j][tx] = Vh[(size_t)(s0 + ty + j) * HDIM + d0 + tx];
    __syncthreads();
    size_t obase = (size_t)bh * HDIM * SEQ;
#pragma unroll
    for (int j = 0; j < 32; j += 8) {
        float v = t[tx][ty + j];   // = V[s0+tx][d0+ty+j]
        __nv_bfloat16 h = __float2bfloat16(v);
        __nv_bfloat16 l = __float2bfloat16(v - __bfloat162float(h));
        size_t o = obase + (size_t)(d0 + ty + j) * SEQ + s0 + tx;
        vthi[o] = h;
        vtlo[o] = l;
    }
}

// ============================ HMMA GEMM (R10, unchanged) ===================
#define BK 64
#define KT_STEPS (KDIM / BK)     // 64
#define ARR 18432                // 128 * 144 bytes
#define GEMM_SMEM (4 * ARR)      // 73728

template<int EPI>
__global__ void __launch_bounds__(256, 2)
hmma_gemm_kernel(const __nv_bfloat16* __restrict__ Ahi,
                 const __nv_bfloat16* __restrict__ Alo,
                 const __nv_bfloat16* __restrict__ Bhi,
                 const __nv_bfloat16* __restrict__ Blo,
                 float* __restrict__ C)
{
    extern __shared__ __align__(16) char smem[];
    const uint32_t sbase = smem_to_u32(smem);

    const int tid  = threadIdx.x;
    const int lane = tid & 31;
    const int wid  = tid >> 5;
    const int wm   = wid >> 2;
    const int wn   = wid & 3;
    const int bm   = blockIdx.y * 128;
    const int bn   = blockIdx.x * 128;

    const __nv_bfloat16* garr[4] = {Ahi, Alo, Bhi, Blo};

    const uint32_t a_lane = (uint32_t)(lane & 15) * 144 + (uint32_t)(lane >> 4) * 16;
    const uint32_t b_row  = (uint32_t)((lane & 7) | ((lane >> 4) << 3));
    const uint32_t b_lane = b_row * 144 + (uint32_t)((lane >> 3) & 1) * 16;

    float acc[4][4][4];
#pragma unroll
    for (int i = 0; i < 4; i++)
#pragma unroll
        for (int j = 0; j < 4; j++)
#pragma unroll
            for (int r = 0; r < 4; r++) acc[i][j][r] = 0.f;

    for (int kt = 0; kt < KT_STEPS; kt++) {
        const int k0 = kt * BK;
        __syncthreads();
#pragma unroll
        for (int i = 0; i < 16; i++) {
            int arr  = i >> 2;
            int rem  = ((i & 3) << 8) + tid;
            int row  = rem >> 3;
            int part = rem & 7;
            int rbase = (arr < 2) ? bm : bn;
            const uint4* gp = (const uint4*)(garr[arr] + ((size_t)(rbase + row) * KDIM + k0 + part * 8));
            uint4 v = *gp;
            *(uint4*)(smem + arr * ARR + row * 144 + part * 16) = v;
        }
        __syncthreads();

#pragma unroll
        for (int ks = 0; ks < 4; ks++) {
            const uint32_t kb = (uint32_t)ks * 32;

            uint32_t a[4][4], bh[2][4], bl[2][4];
#pragma unroll
            for (int mt = 0; mt < 4; mt++)
                ldmatrix_x4(a[mt][0], a[mt][1], a[mt][2], a[mt][3],
                            sbase + (uint32_t)(wm * 64 + mt * 16) * 144 + kb + a_lane);
#pragma unroll
            for (int n2 = 0; n2 < 2; n2++)
                ldmatrix_x4(bh[n2][0], bh[n2][1], bh[n2][2], bh[n2][3],
                            sbase + 2u * ARR + (uint32_t)(wn * 32 + n2 * 16) * 144 + kb + b_lane);
#pragma unroll
            for (int n2 = 0; n2 < 2; n2++)
                ldmatrix_x4(bl[n2][0], bl[n2][1], bl[n2][2], bl[n2][3],
                            sbase + 3u * ARR + (uint32_t)(wn * 32 + n2 * 16) * 144 + kb + b_lane);

#pragma unroll
            for (int mt = 0; mt < 4; mt++)
#pragma unroll
                for (int nt = 0; nt < 4; nt++) {
                    mma_bf16(acc[mt][nt], a[mt],
                             bh[nt >> 1][(nt & 1) * 2], bh[nt >> 1][(nt & 1) * 2 + 1]);
                    mma_bf16(acc[mt][nt], a[mt],
                             bl[nt >> 1][(nt & 1) * 2], bl[nt >> 1][(nt & 1) * 2 + 1]);
                }

#pragma unroll
            for (int mt = 0; mt < 4; mt++)
                ldmatrix_x4(a[mt][0], a[mt][1], a[mt][2], a[mt][3],
                            sbase + ARR + (uint32_t)(wm * 64 + mt * 16) * 144 + kb + a_lane);
#pragma unroll
            for (int mt = 0; mt < 4; mt++)
#pragma unroll
                for (int nt = 0; nt < 4; nt++)
                    mma_bf16(acc[mt][nt], a[mt],
                             bh[nt >> 1][(nt & 1) * 2], bh[nt >> 1][(nt & 1) * 2 + 1]);
        }
    }

#pragma unroll
    for (int mt = 0; mt < 4; mt++) {
#pragma unroll
        for (int half = 0; half < 2; half++) {
            int row = bm + wm * 64 + mt * 16 + (lane >> 2) + half * 8;
#pragma unroll
            for (int nt = 0; nt < 4; nt++) {
                int col = bn + wn * 32 + nt * 8 + (lane & 3) * 2;
                float v0 = acc[mt][nt][half * 2 + 0];
                float v1 = acc[mt][nt][half * 2 + 1];
                if (EPI == 0) {
                    C[(size_t)row * HID + col]     = v0;
                    C[(size_t)row * HID + col + 1] = v1;
                } else {
                    int b = row >> 10, s = row & 1023;
                    int part = col >> 12;
                    int rem  = col & 4095;
                    int h    = rem >> 7;
                    int d    = rem & 127;
                    size_t idx = ((((size_t)(part * BATCH + b) * NHEAD + h) * SEQ + s) * HDIM) + d;
                    C[idx]     = v0;
                    C[idx + 1] = v1;
                }
            }
        }
    }
}

// ============================ RoPE -> bf16 hi/lo ===========================
__global__ void rope_kernel(const float* __restrict__ qkv,
                            __nv_bfloat16* __restrict__ qhi, __nv_bfloat16* __restrict__ qlo,
                            __nv_bfloat16* __restrict__ khi, __nv_bfloat16* __restrict__ klo)
{
    int s  = blockIdx.x;
    int pb = blockIdx.y;
    int part = pb >> 7;
    int bh   = pb & 127;
    int d    = threadIdx.x;

    float p = (float)s;
    float e = (float)(2 * d) * (1.0f / 128.0f);
    float inv_freq = 1.0f / powf(10000.0f, e);
    float freq = p * inv_freq;
    float c = cosf(freq);
    float sn = sinf(freq);

    size_t base = ((size_t)(part * BATCH * NHEAD + bh) * SEQ + s) * HDIM;
    float x1 = qkv[base + d];
    float x2 = qkv[base + d + 64];
    float y1 = x1 * c - x2 * sn;
    float y2 = x2 * c + x1 * sn;

    __nv_bfloat16* hi = part ? khi : qhi;
    __nv_bfloat16* lo = part ? klo : qlo;
    size_t ob = ((size_t)bh * SEQ + s) * HDIM;
    __nv_bfloat16 h1 = __float2bfloat16(y1);
    __nv_bfloat16 h2 = __float2bfloat16(y2);
    hi[ob + d]      = h1;
    hi[ob + d + 64] = h2;
    lo[ob + d]      = __float2bfloat16(y1 - __bfloat162float(h1));
    lo[ob + d + 64] = __float2bfloat16(y2 - __bfloat162float(h2));
}

// ============================ HMMA flash attention =========================
// 128 threads (4 warps), BM=BN=64, D=128. Warp w owns q rows [w*16, w*16+16).
// S = QK^T bf16x3 (fp32 acc), online softmax on C-fragments, P hi/lo split,
// O += P@V bf16x3 with V^T in smem (GEMM-proven ldmatrix B addressing).
#define AT_QROW 272
#define AT_VROW 144
#define AT_QHI 0
#define AT_QLO 17408
#define AT_KHI 34816
#define AT_KLO 52224
#define AT_VHI 69632
#define AT_VLO 88064
#define ATTN_SMEM 106496

__global__ void __launch_bounds__(128)
attn_kernel(const __nv_bfloat16* __restrict__ qhi, const __nv_bfloat16* __restrict__ qlo,
            const __nv_bfloat16* __restrict__ khi, const __nv_bfloat16* __restrict__ klo,
            const __nv_bfloat16* __restrict__ vthi, const __nv_bfloat16* __restrict__ vtlo,
            __nv_bfloat16* __restrict__ out_hi, __nv_bfloat16* __restrict__ out_lo)
{
    extern __shared__ __align__(16) char sm[];
    const uint32_t sb = smem_to_u32(sm);

    const int tid  = threadIdx.x;
    const int lane = tid & 31;
    const int w    = tid >> 5;
    const int qt   = blockIdx.x;
    const int bh   = blockIdx.y;
    const int b    = bh >> 5;
    const int h    = bh & 31;
    const int q0   = qt * 64;
    const size_t hoff  = (size_t)bh * SEQ * HDIM;
    const size_t vbase = (size_t)bh * HDIM * SEQ;

    // ldmatrix lane offsets
    const uint32_t a_lane  = (uint32_t)(lane & 15) * AT_QROW + (uint32_t)(lane >> 4) * 16;
    const uint32_t b_row   = (uint32_t)((lane & 7) | ((lane >> 4) << 3));
    const uint32_t bk_lane = b_row * AT_QROW + (uint32_t)((lane >> 3) & 1) * 16;
    const uint32_t bv_lane = b_row * AT_VROW + (uint32_t)((lane >> 3) & 1) * 16;

    // ---- load Q hi/lo (64 rows x 128 bf16, 272B rows) ----
    for (int i = tid; i < 2048; i += 128) {
        int arr = i >> 10, rem = i & 1023;
        int r = rem >> 4, c = rem & 15;
        const __nv_bfloat16* src = (arr ? qlo : qhi) + hoff + (size_t)(q0 + r) * HDIM + c * 8;
        uint4 v = *(const uint4*)src;
        *(uint4*)(sm + (arr ? AT_QLO : AT_QHI) + r * AT_QROW + c * 16) = v;
    }

    const int g = lane >> 2;           // row-in-tile group
    const int qq0 = q0 + w * 16 + g;   // global q row (first half)
    const int qq1 = qq0 + 8;
    const float scale = 0.08838834764831845f;

    float oa[16][4];
#pragma unroll
    for (int i = 0; i < 16; i++)
#pragma unroll
        for (int r = 0; r < 4; r++) oa[i][r] = 0.f;
    float m0 = -1e30f, m1 = -1e30f, l0 = 0.f, l1 = 0.f;

    for (int kt = 0; kt <= qt; kt++) {
        const int k0 = kt * 64;
        __syncthreads();
        // ---- load K hi/lo (64x128, 272B rows) + Vt hi/lo (128x64, 144B rows)
        for (int i = tid; i < 4096; i += 128) {
            if (i < 2048) {
                int arr = i >> 10, rem = i & 1023;
                int r = rem >> 4, c = rem & 15;
                const __nv_bfloat16* src = (arr ? klo : khi) + hoff + (size_t)(k0 + r) * HDIM + c * 8;
                uint4 v = *(const uint4*)src;
                *(uint4*)(sm + (arr ? AT_KLO : AT_KHI) + r * AT_QROW + c * 16) = v;
            } else {
                int i2 = i - 2048;
                int arr = i2 >> 10, rem = i2 & 1023;
                int r = rem >> 3, c = rem & 7;
                const __nv_bfloat16* src = (arr ? vtlo : vthi) + vbase + (size_t)r * SEQ + k0 + c * 8;
                uint4 v = *(const uint4*)src;
                *(uint4*)(sm + (arr ? AT_VLO : AT_VHI) + r * AT_VROW + c * 16) = v;
            }
        }
        __syncthreads();

        // ---- S = QK^T (bf16x3) ----
        float sc[8][4];
#pragma unroll
        for (int j = 0; j < 8; j++)
#pragma unroll
            for (int r = 0; r < 4; r++) sc[j][r] = 0.f;

#pragma unroll
        for (int ks = 0; ks < 8; ks++) {
            const uint32_t kb = (uint32_t)ks * 32;
            uint32_t ah[4], al[4], kh[4][4], kl[4][4];
            ldmatrix_x4(ah[0], ah[1], ah[2], ah[3],
                        sb + AT_QHI + (uint32_t)(w * 16) * AT_QROW + kb + a_lane);
            ldmatrix_x4(al[0], al[1], al[2], al[3],
                        sb + AT_QLO + (uint32_t)(w * 16) * AT_QROW + kb + a_lane);
#pragma unroll
            for (int j2 = 0; j2 < 4; j2++) {
                ldmatrix_x4(kh[j2][0], kh[j2][1], kh[j2][2], kh[j2][3],
                            sb + AT_KHI + (uint32_t)(j2 * 16) * AT_QROW + kb + bk_lane);
                ldmatrix_x4(kl[j2][0], kl[j2][1], kl[j2][2], kl[j2][3],
                            sb + AT_KLO + (uint32_t)(j2 * 16) * AT_QROW + kb + bk_lane);
            }
#pragma unroll
            for (int j = 0; j < 8; j++) {
                uint32_t b0h = kh[j >> 1][(j & 1) * 2], b1h = kh[j >> 1][(j & 1) * 2 + 1];
                uint32_t b0l = kl[j >> 1][(j & 1) * 2], b1l = kl[j >> 1][(j & 1) * 2 + 1];
                mma_bf16(sc[j], ah, b0h, b1h);
                mma_bf16(sc[j], ah, b0l, b1l);
                mma_bf16(sc[j], al, b0h, b1h);
            }
        }

        // ---- scale (+ causal mask on diagonal tile) ----
        if (kt == qt) {
#pragma unroll
            for (int j = 0; j < 8; j++) {
                int c0 = k0 + j * 8 + (lane & 3) * 2;
                sc[j][0] = sc[j][0] * scale + ((c0     <= qq0) ? 0.f : -1e9f);
                sc[j][1] = sc[j][1] * scale + ((c0 + 1 <= qq0) ? 0.f : -1e9f);
                sc[j][2] = sc[j][2] * scale + ((c0     <= qq1) ? 0.f : -1e9f);
                sc[j][3] = sc[j][3] * scale + ((c0 + 1 <= qq1) ? 0.f : -1e9f);
            }
        } else {
#pragma unroll
            for (int j = 0; j < 8; j++)
#pragma unroll
                for (int r = 0; r < 4; r++) sc[j][r] *= scale;
        }

        // ---- online softmax (rows g, g+8; stats across quad lanes) ----
        float mx0 = -1e30f, mx1 = -1e30f;
#pragma unroll
        for (int j = 0; j < 8; j++) {
            mx0 = fmaxf(mx0, fmaxf(sc[j][0], sc[j][1]));
            mx1 = fmaxf(mx1, fmaxf(sc[j][2], sc[j][3]));
        }
        mx0 = fmaxf(mx0, __shfl_xor_sync(0xffffffffu, mx0, 1));
        mx0 = fmaxf(mx0, __shfl_xor_sync(0xffffffffu, mx0, 2));
        mx1 = fmaxf(mx1, __shfl_xor_sync(0xffffffffu, mx1, 1));
        mx1 = fmaxf(mx1, __shfl_xor_sync(0xffffffffu, mx1, 2));
        float mn0 = fmaxf(m0, mx0), mn1 = fmaxf(m1, mx1);
        float al0 = __expf(m0 - mn0), al1 = __expf(m1 - mn1);

        float s0 = 0.f, s1 = 0.f;
#pragma unroll
        for (int j = 0; j < 8; j++) {
            sc[j][0] = __expf(sc[j][0] - mn0); s0 += sc[j][0];
            sc[j][1] = __expf(sc[j][1] - mn0); s0 += sc[j][1];
            sc[j][2] = __expf(sc[j][2] - mn1); s1 += sc[j][2];
            sc[j][3] = __expf(sc[j][3] - mn1); s1 += sc[j][3];
        }
        s0 += __shfl_xor_sync(0xffffffffu, s0, 1);
        s0 += __shfl_xor_sync(0xffffffffu, s0, 2);
        s1 += __shfl_xor_sync(0xffffffffu, s1, 1);
        s1 += __shfl_xor_sync(0xffffffffu, s1, 2);
        l0 = l0 * al0 + s0; m0 = mn0;
        l1 = l1 * al1 + s1; m1 = mn1;

#pragma unroll
        for (int i = 0; i < 16; i++) {
            oa[i][0] *= al0; oa[i][1] *= al0;
            oa[i][2] *= al1; oa[i][3] *= al1;
        }

        // ---- P -> A fragments (hi + residual lo) ----
        uint32_t pfh[4][4], pfl[4][4];
#pragma unroll
        for (int t = 0; t < 4; t++) {
            int j = 2 * t;
            pfh[t][0] = pack_bf16x2(sc[j][0],     sc[j][1]);
            pfh[t][1] = pack_bf16x2(sc[j][2],     sc[j][3]);
            pfh[t][2] = pack_bf16x2(sc[j + 1][0], sc[j + 1][1]);
            pfh[t][3] = pack_bf16x2(sc[j + 1][2], sc[j + 1][3]);
            pfl[t][0] = pack_bf16x2(bf16_res(sc[j][0]),     bf16_res(sc[j][1]));
            pfl[t][1] = pack_bf16x2(bf16_res(sc[j][2]),     bf16_res(sc[j][3]));
            pfl[t][2] = pack_bf16x2(bf16_res(sc[j + 1][0]), bf16_res(sc[j + 1][1]));
            pfl[t][3] = pack_bf16x2(bf16_res(sc[j + 1][2]), bf16_res(sc[j + 1][3]));
        }

        // ---- O += P @ V (bf16x3) ----
#pragma unroll
        for (int t = 0; t < 4; t++) {
            const uint32_t kb = (uint32_t)t * 32;
#pragma unroll
            for (int n2 = 0; n2 < 8; n2++) {
                uint32_t vh[4], vl[4];
                ldmatrix_x4(vh[0], vh[1], vh[2], vh[3],
                            sb + AT_VHI + (uint32_t)(n2 * 16) * AT_VROW + kb + bv_lane);
                ldmatrix_x4(vl[0], vl[1], vl[2], vl[3],
                            sb + AT_VLO + (uint32_t)(n2 * 16) * AT_VROW + kb + bv_lane);
#pragma unroll
                for (int q = 0; q < 2; q++) {
                    int nt = n2 * 2 + q;
                    mma_bf16(oa[nt], pfh[t], vh[q * 2], vh[q * 2 + 1]);
                    mma_bf16(oa[nt], pfh[t], vl[q * 2], vl[q * 2 + 1]);
                    mma_bf16(oa[nt], pfl[t], vh[q * 2], vh[q * 2 + 1]);
                }
            }
        }
    }

    // ---- epilogue: normalize, split, store [b][s][h*128+d] ----
    float il0 = 1.f / l0, il1 = 1.f / l1;
    size_t base0 = ((size_t)(b * SEQ + qq0)) * HID + (size_t)h * HDIM;
    size_t base1 = ((size_t)(b * SEQ + qq1)) * HID + (size_t)h * HDIM;
#pragma unroll
    for (int nt = 0; nt < 16; nt++) {
        int d = nt * 8 + (lane & 3) * 2;
        float v00 = oa[nt][0] * il0, v01 = oa[nt][1] * il0;
        float v10 = oa[nt][2] * il1, v11 = oa[nt][3] * il1;
        *(uint32_t*)(out_hi + base0 + d) = pack_bf16x2(v00, v01);
        *(uint32_t*)(out_lo + base0 + d) = pack_bf16x2(bf16_res(v00), bf16_res(v01));
        *(uint32_t*)(out_hi + base1 + d) = pack_bf16x2(v10, v11);
        *(uint32_t*)(out_lo + base1 + d) = pack_bf16x2(bf16_res(v10), bf16_res(v11));
    }
}

// ============================ launch =======================================
extern "C" void kernel_launch(void* const* d_in, const int* in_sizes, int n_in,
                              void* d_out, int out_size)
{
    const float* hidden = (const float*)d_in[0];
    const float* Wp     = (const float*)d_in[1];
    const float* Wo     = (const float*)d_in[2];
    float* out = (float*)d_out;

    float *qkv = nullptr;
    __nv_bfloat16 *a1hi, *a1lo, *bphi, *bplo, *bohi, *bolo, *athi, *atlo;
    __nv_bfloat16 *qhi, *qlo, *khi, *klo, *vthi, *vtlo;
    cudaGetSymbolAddress((void**)&qkv,  g_qkv);
    cudaGetSymbolAddress((void**)&a1hi, g_a1hi);
    cudaGetSymbolAddress((void**)&a1lo, g_a1lo);
    cudaGetSymbolAddress((void**)&bphi, g_bphi);
    cudaGetSymbolAddress((void**)&bplo, g_bplo);
    cudaGetSymbolAddress((void**)&bohi, g_bohi);
    cudaGetSymbolAddress((void**)&bolo, g_bolo);
    cudaGetSymbolAddress((void**)&athi, g_athi);
    cudaGetSymbolAddress((void**)&atlo, g_atlo);
    cudaGetSymbolAddress((void**)&qhi,  g_qhi);
    cudaGetSymbolAddress((void**)&qlo,  g_qlo);
    cudaGetSymbolAddress((void**)&khi,  g_khi);
    cudaGetSymbolAddress((void**)&klo,  g_klo);
    cudaGetSymbolAddress((void**)&vthi, g_vthi);
    cudaGetSymbolAddress((void**)&vtlo, g_vtlo);

    // Prep: split hidden; transpose+split weights
    split_kernel<<<(M_ROWS * KDIM / 4 + 255) / 256, 256>>>(hidden, a1hi, a1lo, M_ROWS * KDIM / 4);
    transpose_split_kernel<<<dim3(QKV_N / 32, KDIM / 32), dim3(32, 8)>>>(Wp, bphi, bplo, KDIM, QKV_N);
    transpose_split_kernel<<<dim3(HID  / 32, KDIM / 32), dim3(32, 8)>>>(Wo, bohi, bolo, KDIM, HID);

    cudaFuncSetAttribute(hmma_gemm_kernel<0>, cudaFuncAttributeMaxDynamicSharedMemorySize, GEMM_SMEM);
    cudaFuncSetAttribute(hmma_gemm_kernel<1>, cudaFuncAttributeMaxDynamicSharedMemorySize, GEMM_SMEM);
    cudaFuncSetAttribute(attn_kernel, cudaFuncAttributeMaxDynamicSharedMemorySize, ATTN_SMEM);

    // GEMM1: QKV projection -> g_qkv head-major fp32
    hmma_gemm_kernel<1><<<dim3(QKV_N / 128, M_ROWS / 128), 256, GEMM_SMEM>>>(
        a1hi, a1lo, bphi, bplo, qkv);

    // RoPE -> Q/K bf16 hi/lo; V -> V^T bf16 hi/lo
    rope_kernel<<<dim3(SEQ, 2 * BATCH * NHEAD), 64>>>(qkv, qhi, qlo, khi, klo);
    vtrans_kernel<<<dim3(HDIM / 32, SEQ / 32, BATCH * NHEAD), dim3(32, 8)>>>(
        qkv + 2ull * HEAD_ELEMS, vthi, vtlo);

    // Flash attention (HMMA) -> bf16 hi/lo
    attn_kernel<<<dim3(SEQ / 64, BATCH * NHEAD), 128, ATTN_SMEM>>>(
        qhi, qlo, khi, klo, vthi, vtlo, athi, atlo);

    // GEMM2: output projection
    hmma_gemm_kernel<0><<<dim3(HID / 128, M_ROWS / 128), 256, GEMM_SMEM>>>(
        athi, atlo, bohi, bolo, out);
}